// round 2
// baseline (speedup 1.0000x reference)
#include <cuda_runtime.h>
#include <math.h>

// ---------------------------------------------------------------------------
// Problem constants
// ---------------------------------------------------------------------------
#define B_     2
#define C_IN   64
#define T_IN   16
#define H_IN   48
#define W_IN   48
#define tT     8
#define tH     24
#define tW     24
#define NTOK   4608        // tT*tH*tW
#define CD     32          // down channels
#define CQ     16
#define CV     32
#define NOUT   (B_*C_IN*T_IN*H_IN*W_IN)   // 14745600

// ---------------------------------------------------------------------------
// Scratch (static device globals — no allocation)
// ---------------------------------------------------------------------------
__device__ float g_xd[2][B_][NTOK][CD];      // [sel: 0=x_down, 1=xc_down]
__device__ float g_q [2][B_][NTOK][CQ];      // [a: 0=cross, 1=self] (pre-scaled by 1/2)
__device__ float g_k [2][B_][NTOK][CQ];
__device__ float g_v [2][B_][NTOK][CV];
__device__ float g_o [2][B_][NTOK][CV];      // attention outputs
__device__ float g_mu[2][B_];
__device__ float g_rs[2][B_];
__device__ float g_u [2][B_][C_IN][NTOK];    // up-conv outputs at low res

// ---------------------------------------------------------------------------
// Kernel 1: trilinear downsample (16,48,48)->(8,24,24) + 1x1 conv 64->32
// grid: (tT*tH=192, B_, 2 sel)  block: 128
// ---------------------------------------------------------------------------
__global__ __launch_bounds__(128) void k1_down(
    const float* __restrict__ x, const float* __restrict__ xc,
    const float* __restrict__ wd, const float* __restrict__ bd,
    const float* __restrict__ wdc, const float* __restrict__ bdc)
{
    __shared__ float rs[C_IN][tW];
    const int sel = blockIdx.z;
    const int b   = blockIdx.y;
    const int tq  = blockIdx.x / tH;
    const int hq  = blockIdx.x % tH;
    const float* in = sel ? xc : x;
    const float* Wm = sel ? wdc : wd;
    const float* Bm = sel ? bdc : bd;

    const float st = (float)(15.0 / 7.0);
    const float sh = (float)(47.0 / 23.0);

    float pt = (float)tq * st;
    int t0 = (int)floorf(pt); t0 = t0 < 0 ? 0 : (t0 > T_IN-1 ? T_IN-1 : t0);
    int t1 = t0 + 1 > T_IN-1 ? T_IN-1 : t0 + 1;
    float ft = pt - (float)t0;

    float ph = (float)hq * sh;
    int h0 = (int)floorf(ph); h0 = h0 < 0 ? 0 : (h0 > H_IN-1 ? H_IN-1 : h0);
    int h1 = h0 + 1 > H_IN-1 ? H_IN-1 : h0 + 1;
    float fh = ph - (float)h0;

    const int tid = threadIdx.x;
    for (int e = tid; e < C_IN * tW; e += 128) {
        int c = e / tW, w = e % tW;
        float pw = (float)w * sh;
        int w0 = (int)floorf(pw); w0 = w0 < 0 ? 0 : (w0 > W_IN-1 ? W_IN-1 : w0);
        int w1 = w0 + 1 > W_IN-1 ? W_IN-1 : w0 + 1;
        float fw = pw - (float)w0;
        const float* base = in + ((size_t)(b * C_IN + c) * T_IN) * (H_IN * W_IN);
        const float* p00 = base + t0 * (H_IN*W_IN) + h0 * W_IN;
        const float* p01 = base + t0 * (H_IN*W_IN) + h1 * W_IN;
        const float* p10 = base + t1 * (H_IN*W_IN) + h0 * W_IN;
        const float* p11 = base + t1 * (H_IN*W_IN) + h1 * W_IN;
        float v00 = p00[w0] + (p00[w1] - p00[w0]) * fw;
        float v01 = p01[w0] + (p01[w1] - p01[w0]) * fw;
        float v10 = p10[w0] + (p10[w1] - p10[w0]) * fw;
        float v11 = p11[w0] + (p11[w1] - p11[w0]) * fw;
        float v0 = v00 + (v01 - v00) * fh;
        float v1 = v10 + (v11 - v10) * fh;
        rs[c][w] = v0 + (v1 - v0) * ft;
    }
    __syncthreads();
    for (int e = tid; e < CD * tW; e += 128) {
        int co = e & 31, w = e >> 5;
        float acc = Bm[co];
        #pragma unroll 8
        for (int c = 0; c < C_IN; ++c) acc += Wm[co * C_IN + c] * rs[c][w];
        int n = (tq * tH + hq) * tW + w;
        g_xd[sel][b][n][co] = acc;
    }
}

// ---------------------------------------------------------------------------
// Kernel 2: QKV projections + RoPE. grid (NTOK, B_), block 96
// ---------------------------------------------------------------------------
__global__ __launch_bounds__(96) void k2_qkv(
    const float* __restrict__ wq,  const float* __restrict__ bq,
    const float* __restrict__ wk,  const float* __restrict__ bk,
    const float* __restrict__ wv,  const float* __restrict__ bv,
    const float* __restrict__ wqs, const float* __restrict__ bqs,
    const float* __restrict__ wks, const float* __restrict__ bks,
    const float* __restrict__ wvs, const float* __restrict__ bvs,
    const float* __restrict__ off, const float* __restrict__ offc)
{
    const int n = blockIdx.x, b = blockIdx.y;
    const int t = n / (tH * tW);
    __shared__ float xs[CD], xcs[CD];
    const int tid = threadIdx.x;
    if (tid < 32)        xs[tid]       = g_xd[0][b][n][tid];
    else if (tid < 64)   xcs[tid - 32] = g_xd[1][b][n][tid - 32];
    __syncthreads();

    if (tid < 32) {
        int role = tid >> 3, j = tid & 7;
        const float* src = (role == 0) ? xs : xcs;
        const float *Wm, *Bm, *op;
        if      (role == 0) { Wm = wq;  Bm = bq;  op = off;  }
        else if (role == 1) { Wm = wk;  Bm = bk;  op = offc; }
        else if (role == 2) { Wm = wqs; Bm = bqs; op = off;  }
        else                { Wm = wks; Bm = bks; op = off;  }
        float x1 = Bm[j], x2 = Bm[j + 8];
        #pragma unroll 8
        for (int c = 0; c < 32; ++c) {
            float xv = src[c];
            x1 += Wm[j * 32 + c] * xv;
            x2 += Wm[(j + 8) * 32 + c] * xv;
        }
        float invf = __powf(10000.0f, -((float)(2 * j)) / 16.0f);
        float arg  = (float)t * invf;
        float o    = op[j * 500 + t];
        float sv = sinf(arg) + o;
        float cv = cosf(arg) + o;
        float o1 = x1 * cv - x2 * sv;
        float o2 = x2 * cv + x1 * sv;
        if (role == 0)      { g_q[0][b][n][j] = o1 * 0.5f; g_q[0][b][n][j+8] = o2 * 0.5f; }
        else if (role == 1) { g_k[0][b][n][j] = o1;        g_k[0][b][n][j+8] = o2; }
        else if (role == 2) { g_q[1][b][n][j] = o1 * 0.5f; g_q[1][b][n][j+8] = o2 * 0.5f; }
        else                { g_k[1][b][n][j] = o1;        g_k[1][b][n][j+8] = o2; }
    } else {
        int av = (tid >= 64) ? 1 : 0;
        int c  = tid - 32 - av * 32;
        const float* Wm = av ? wvs : wv;
        const float* Bm = av ? bvs : bv;
        float acc = Bm[c];
        #pragma unroll 8
        for (int ci = 0; ci < 32; ++ci) acc += Wm[c * 32 + ci] * xcs[ci];
        g_v[av][b][n][c] = acc;
    }
}

// ---------------------------------------------------------------------------
// Kernel 3: attention. One block = 64 query rows, loops 72 tiles of 64 keys.
// Softmax without max-subtraction (scores bounded, |s| < ~3).
// grid (72, 4), block 128.
// ---------------------------------------------------------------------------
__global__ __launch_bounds__(128) void k3_attn()
{
    const int a = blockIdx.y >> 1, b = blockIdx.y & 1;
    const int row0 = blockIdx.x * 64;
    const float* Q = &g_q[a][b][0][0];
    const float* K = &g_k[a][b][0][0];
    const float* V = &g_v[a][b][0][0];

    __shared__ float Qs[CQ][64];
    __shared__ float Ks[CQ][64];
    __shared__ float Vs[64][CV];
    __shared__ float Ss[64][65];      // scores -> probabilities in place
    __shared__ float Lrow[64];

    const int tid = threadIdx.x;
    const int rg = tid >> 3;          // 0..15 : 4 rows each
    const int mg = tid & 7;           // 0..7  : 8 score cols / 4 PV cols

    // Q tile transposed into smem
    for (int e = tid; e < 256; e += 128) {
        int m = e >> 2, c4 = (e & 3) << 2;
        float4 qv = *(const float4*)(Q + (size_t)(row0 + m) * CQ + c4);
        Qs[c4][m] = qv.x; Qs[c4+1][m] = qv.y; Qs[c4+2][m] = qv.z; Qs[c4+3][m] = qv.w;
    }

    float acc[4][4];
    #pragma unroll
    for (int i = 0; i < 4; ++i)
        #pragma unroll
        for (int j = 0; j < 4; ++j) acc[i][j] = 0.f;
    float lsum = 0.f;

    __syncthreads();

    for (int mt = 0; mt < NTOK / 64; ++mt) {
        const int m0 = mt * 64;
        for (int e = tid; e < 256; e += 128) {
            int m = e >> 2, c4 = (e & 3) << 2;
            float4 kv = *(const float4*)(K + (size_t)(m0 + m) * CQ + c4);
            Ks[c4][m] = kv.x; Ks[c4+1][m] = kv.y; Ks[c4+2][m] = kv.z; Ks[c4+3][m] = kv.w;
        }
        for (int e = tid; e < 512; e += 128) {
            int m = e >> 3, c4 = (e & 7) << 2;
            *(float4*)&Vs[m][c4] = *(const float4*)(V + (size_t)(m0 + m) * CV + c4);
        }
        __syncthreads();

        // ---- scores: S[rg*4+i][mg*8+j] = q . k (q pre-scaled by 1/2) ----
        float s[4][8];
        #pragma unroll
        for (int i = 0; i < 4; ++i)
            #pragma unroll
            for (int j = 0; j < 8; ++j) s[i][j] = 0.f;
        #pragma unroll 4
        for (int c = 0; c < CQ; ++c) {
            float4 qv = *(const float4*)&Qs[c][rg << 2];
            float4 k0 = *(const float4*)&Ks[c][mg << 3];
            float4 k1 = *(const float4*)&Ks[c][(mg << 3) + 4];
            float qa[4] = {qv.x, qv.y, qv.z, qv.w};
            float kb[8] = {k0.x, k0.y, k0.z, k0.w, k1.x, k1.y, k1.z, k1.w};
            #pragma unroll
            for (int i = 0; i < 4; ++i)
                #pragma unroll
                for (int j = 0; j < 8; ++j)
                    s[i][j] += qa[i] * kb[j];
        }
        #pragma unroll
        for (int i = 0; i < 4; ++i)
            #pragma unroll
            for (int j = 0; j < 8; ++j)
                Ss[(rg << 2) + i][(mg << 3) + j] = s[i][j];
        __syncthreads();

        // ---- exp in place + row partial sums (threads 0..63, one row each) ----
        if (tid < 64) {
            float rsum = 0.f;
            #pragma unroll 8
            for (int m = 0; m < 64; ++m) {
                float p = __expf(Ss[tid][m]);
                Ss[tid][m] = p;
                rsum += p;
            }
            lsum += rsum;
        }
        __syncthreads();

        // ---- PV: acc[rg*4+i][mg*4+j] += P[r][m] * V[m][c] ----
        const int rg4 = rg << 2;
        #pragma unroll 8
        for (int m = 0; m < 64; ++m) {
            float4 vv = *(const float4*)&Vs[m][mg << 2];
            float p0 = Ss[rg4 + 0][m];
            float p1 = Ss[rg4 + 1][m];
            float p2 = Ss[rg4 + 2][m];
            float p3 = Ss[rg4 + 3][m];
            acc[0][0] += p0 * vv.x; acc[0][1] += p0 * vv.y; acc[0][2] += p0 * vv.z; acc[0][3] += p0 * vv.w;
            acc[1][0] += p1 * vv.x; acc[1][1] += p1 * vv.y; acc[1][2] += p1 * vv.z; acc[1][3] += p1 * vv.w;
            acc[2][0] += p2 * vv.x; acc[2][1] += p2 * vv.y; acc[2][2] += p2 * vv.z; acc[2][3] += p2 * vv.w;
            acc[3][0] += p3 * vv.x; acc[3][1] += p3 * vv.y; acc[3][2] += p3 * vv.z; acc[3][3] += p3 * vv.w;
        }
        __syncthreads();
    }

    if (tid < 64) Lrow[tid] = lsum;
    __syncthreads();
    #pragma unroll
    for (int i = 0; i < 4; ++i) {
        int r = (rg << 2) + i;
        float inv = 1.f / Lrow[r];
        float4 o = make_float4(acc[i][0]*inv, acc[i][1]*inv, acc[i][2]*inv, acc[i][3]*inv);
        *(float4*)&g_o[a][b][row0 + r][mg << 2] = o;
    }
}

// ---------------------------------------------------------------------------
// Kernel 4: groupnorm stats (mean/var over all C,T,H,W per batch). grid 4.
// ---------------------------------------------------------------------------
__global__ __launch_bounds__(512) void k4_stats()
{
    const int a = blockIdx.x >> 1, b = blockIdx.x & 1;
    const float* p = &g_o[a][b][0][0];
    const int tot = NTOK * CV;
    float s = 0.f, ss = 0.f;
    for (int i = threadIdx.x; i < tot; i += 512) {
        float v = p[i]; s += v; ss += v * v;
    }
    __shared__ float rs[512], rss[512];
    rs[threadIdx.x] = s; rss[threadIdx.x] = ss;
    __syncthreads();
    for (int st = 256; st > 0; st >>= 1) {
        if (threadIdx.x < st) {
            rs[threadIdx.x]  += rs[threadIdx.x + st];
            rss[threadIdx.x] += rss[threadIdx.x + st];
        }
        __syncthreads();
    }
    if (threadIdx.x == 0) {
        float inv = 1.f / (float)tot;
        float mu  = rs[0] * inv;
        float var = rss[0] * inv - mu * mu;
        g_mu[a][b] = mu;
        g_rs[a][b] = rsqrtf(var + 1e-5f);
    }
}

// ---------------------------------------------------------------------------
// Kernel 5: groupnorm apply + 1x1 up-conv 32->64. grid (NTOK, B_), block 128.
// ---------------------------------------------------------------------------
__global__ __launch_bounds__(128) void k5_gnup(
    const float* __restrict__ gw,  const float* __restrict__ gb,
    const float* __restrict__ gws, const float* __restrict__ gbs,
    const float* __restrict__ wu,  const float* __restrict__ bu,
    const float* __restrict__ wus, const float* __restrict__ bus)
{
    const int n = blockIdx.x, b = blockIdx.y;
    __shared__ float h0[CV], h1[CV];
    const int tid = threadIdx.x;
    if (tid < 32) {
        h0[tid] = (g_o[0][b][n][tid] - g_mu[0][b]) * g_rs[0][b] * gw[tid] + gb[tid];
    } else if (tid < 64) {
        int c = tid - 32;
        h1[c] = (g_o[1][b][n][c] - g_mu[1][b]) * g_rs[1][b] * gws[c] + gbs[c];
    }
    __syncthreads();
    if (tid < 64) {
        float acc = bu[tid];
        #pragma unroll 8
        for (int c = 0; c < 32; ++c) acc += wu[tid * 32 + c] * h0[c];
        g_u[0][b][tid][n] = acc;
    } else {
        int co = tid - 64;
        float acc = bus[co];
        #pragma unroll 8
        for (int c = 0; c < 32; ++c) acc += wus[co * 32 + c] * h1[c];
        g_u[1][b][co][n] = acc;
    }
}

// ---------------------------------------------------------------------------
// Kernel 6: trilinear upsample (8,24,24)->(16,48,48) of both branches + combine
// ---------------------------------------------------------------------------
__global__ __launch_bounds__(256) void k6_final(
    const float* __restrict__ xc, float* __restrict__ out)
{
    int idx = blockIdx.x * blockDim.x + threadIdx.x;
    if (idx >= NOUT) return;
    int w = idx % W_IN;
    int h = (idx / W_IN) % H_IN;
    int t = (idx / (W_IN * H_IN)) % T_IN;
    int c = (idx / (W_IN * H_IN * T_IN)) % C_IN;
    int b = idx / (W_IN * H_IN * T_IN * C_IN);

    const float st = (float)(7.0 / 15.0);
    const float sw = (float)(23.0 / 47.0);

    float pt = (float)t * st;
    int t0 = (int)floorf(pt); t0 = t0 < 0 ? 0 : (t0 > tT-1 ? tT-1 : t0);
    int t1 = t0 + 1 > tT-1 ? tT-1 : t0 + 1;
    float ft = pt - (float)t0;

    float ph = (float)h * sw;
    int h0 = (int)floorf(ph); h0 = h0 < 0 ? 0 : (h0 > tH-1 ? tH-1 : h0);
    int h1 = h0 + 1 > tH-1 ? tH-1 : h0 + 1;
    float fh = ph - (float)h0;

    float pw = (float)w * sw;
    int w0 = (int)floorf(pw); w0 = w0 < 0 ? 0 : (w0 > tW-1 ? tW-1 : w0);
    int w1 = w0 + 1 > tW-1 ? tW-1 : w0 + 1;
    float fw = pw - (float)w0;

    int i00 = (t0 * tH + h0) * tW;
    int i01 = (t0 * tH + h1) * tW;
    int i10 = (t1 * tH + h0) * tW;
    int i11 = (t1 * tH + h1) * tW;

    float r[2];
    #pragma unroll
    for (int a = 0; a < 2; ++a) {
        const float* U = &g_u[a][b][c][0];
        float v00 = U[i00 + w0] + (U[i00 + w1] - U[i00 + w0]) * fw;
        float v01 = U[i01 + w0] + (U[i01 + w1] - U[i01 + w0]) * fw;
        float v10 = U[i10 + w0] + (U[i10 + w1] - U[i10 + w0]) * fw;
        float v11 = U[i11 + w0] + (U[i11 + w1] - U[i11 + w0]) * fw;
        float v0 = v00 + (v01 - v00) * fh;
        float v1 = v10 + (v11 - v10) * fh;
        r[a] = v0 + (v1 - v0) * ft;
    }
    out[idx] = xc[idx] + r[1] - 0.5f * r[0];
}

// ---------------------------------------------------------------------------
extern "C" void kernel_launch(void* const* d_in, const int* in_sizes, int n_in,
                              void* d_out, int out_size)
{
    const float* x        = (const float*)d_in[0];
    const float* x_c      = (const float*)d_in[1];
    const float* w_down   = (const float*)d_in[2];
    const float* b_down   = (const float*)d_in[3];
    const float* w_down_c = (const float*)d_in[4];
    const float* b_down_c = (const float*)d_in[5];
    const float* w_q      = (const float*)d_in[6];
    const float* b_q      = (const float*)d_in[7];
    const float* w_k      = (const float*)d_in[8];
    const float* b_k      = (const float*)d_in[9];
    const float* w_v      = (const float*)d_in[10];
    const float* b_v      = (const float*)d_in[11];
    const float* w_q_sa   = (const float*)d_in[12];
    const float* b_q_sa   = (const float*)d_in[13];
    const float* w_k_sa   = (const float*)d_in[14];
    const float* b_k_sa   = (const float*)d_in[15];
    const float* w_v_sa   = (const float*)d_in[16];
    const float* b_v_sa   = (const float*)d_in[17];
    const float* gn_w     = (const float*)d_in[18];
    const float* gn_b     = (const float*)d_in[19];
    const float* gn_w_sa  = (const float*)d_in[20];
    const float* gn_b_sa  = (const float*)d_in[21];
    const float* w_up     = (const float*)d_in[22];
    const float* b_up     = (const float*)d_in[23];
    const float* w_up_sa  = (const float*)d_in[24];
    const float* b_up_sa  = (const float*)d_in[25];
    const float* offset   = (const float*)d_in[26];
    const float* offset_c = (const float*)d_in[27];

    dim3 g1(tT * tH, B_, 2);
    k1_down<<<g1, 128>>>(x, x_c, w_down, b_down, w_down_c, b_down_c);

    dim3 g2(NTOK, B_);
    k2_qkv<<<g2, 96>>>(w_q, b_q, w_k, b_k, w_v, b_v,
                       w_q_sa, b_q_sa, w_k_sa, b_k_sa, w_v_sa, b_v_sa,
                       offset, offset_c);

    dim3 g3(NTOK / 64, 4);
    k3_attn<<<g3, 128>>>();

    k4_stats<<<4, 512>>>();

    dim3 g5(NTOK, B_);
    k5_gnup<<<g5, 128>>>(gn_w, gn_b, gn_w_sa, gn_b_sa,
                         w_up, b_up, w_up_sa, b_up_sa);

    k6_final<<<(NOUT + 255) / 256, 256>>>(x_c, (float*)d_out);
}

// round 3
// speedup vs baseline: 1.0036x; 1.0036x over previous
#include <cuda_runtime.h>
#include <math.h>

// ---------------------------------------------------------------------------
// Problem constants
// ---------------------------------------------------------------------------
#define B_     2
#define C_IN   64
#define T_IN   16
#define H_IN   48
#define W_IN   48
#define tT     8
#define tH     24
#define tW     24
#define NTOK   4608        // tT*tH*tW
#define CD     32          // down channels
#define CQ     16
#define CV     32
#define NOUT   (B_*C_IN*T_IN*H_IN*W_IN)   // 14745600

// ---------------------------------------------------------------------------
// Scratch (static device globals — no allocation)
// ---------------------------------------------------------------------------
__device__ float g_xd[2][B_][NTOK][CD];      // [sel: 0=x_down, 1=xc_down]
__device__ float g_q [2][B_][NTOK][CQ];      // [a: 0=cross, 1=self] (pre-scaled by 1/2)
__device__ float g_k [2][B_][NTOK][CQ];
__device__ float g_v [2][B_][NTOK][CV];
__device__ float g_o [2][B_][NTOK][CV];      // attention outputs
__device__ float g_mu[2][B_];
__device__ float g_rs[2][B_];
__device__ float g_u [2][B_][C_IN][NTOK];    // up-conv outputs at low res

// ---------------------------------------------------------------------------
// Kernel 1: trilinear downsample (16,48,48)->(8,24,24) + 1x1 conv 64->32
// grid: (tT*tH=192, B_, 2 sel)  block: 128
// ---------------------------------------------------------------------------
__global__ __launch_bounds__(128) void k1_down(
    const float* __restrict__ x, const float* __restrict__ xc,
    const float* __restrict__ wd, const float* __restrict__ bd,
    const float* __restrict__ wdc, const float* __restrict__ bdc)
{
    __shared__ float rs[C_IN][tW];
    const int sel = blockIdx.z;
    const int b   = blockIdx.y;
    const int tq  = blockIdx.x / tH;
    const int hq  = blockIdx.x % tH;
    const float* in = sel ? xc : x;
    const float* Wm = sel ? wdc : wd;
    const float* Bm = sel ? bdc : bd;

    const float st = (float)(15.0 / 7.0);
    const float sh = (float)(47.0 / 23.0);

    float pt = (float)tq * st;
    int t0 = (int)floorf(pt); t0 = t0 < 0 ? 0 : (t0 > T_IN-1 ? T_IN-1 : t0);
    int t1 = t0 + 1 > T_IN-1 ? T_IN-1 : t0 + 1;
    float ft = pt - (float)t0;

    float ph = (float)hq * sh;
    int h0 = (int)floorf(ph); h0 = h0 < 0 ? 0 : (h0 > H_IN-1 ? H_IN-1 : h0);
    int h1 = h0 + 1 > H_IN-1 ? H_IN-1 : h0 + 1;
    float fh = ph - (float)h0;

    const int tid = threadIdx.x;
    for (int e = tid; e < C_IN * tW; e += 128) {
        int c = e / tW, w = e % tW;
        float pw = (float)w * sh;
        int w0 = (int)floorf(pw); w0 = w0 < 0 ? 0 : (w0 > W_IN-1 ? W_IN-1 : w0);
        int w1 = w0 + 1 > W_IN-1 ? W_IN-1 : w0 + 1;
        float fw = pw - (float)w0;
        const float* base = in + ((size_t)(b * C_IN + c) * T_IN) * (H_IN * W_IN);
        const float* p00 = base + t0 * (H_IN*W_IN) + h0 * W_IN;
        const float* p01 = base + t0 * (H_IN*W_IN) + h1 * W_IN;
        const float* p10 = base + t1 * (H_IN*W_IN) + h0 * W_IN;
        const float* p11 = base + t1 * (H_IN*W_IN) + h1 * W_IN;
        float v00 = p00[w0] + (p00[w1] - p00[w0]) * fw;
        float v01 = p01[w0] + (p01[w1] - p01[w0]) * fw;
        float v10 = p10[w0] + (p10[w1] - p10[w0]) * fw;
        float v11 = p11[w0] + (p11[w1] - p11[w0]) * fw;
        float v0 = v00 + (v01 - v00) * fh;
        float v1 = v10 + (v11 - v10) * fh;
        rs[c][w] = v0 + (v1 - v0) * ft;
    }
    __syncthreads();
    for (int e = tid; e < CD * tW; e += 128) {
        int co = e & 31, w = e >> 5;
        float acc = Bm[co];
        #pragma unroll 8
        for (int c = 0; c < C_IN; ++c) acc += Wm[co * C_IN + c] * rs[c][w];
        int n = (tq * tH + hq) * tW + w;
        g_xd[sel][b][n][co] = acc;
    }
}

// ---------------------------------------------------------------------------
// Kernel 2: QKV projections + RoPE. grid (NTOK, B_), block 96
// ---------------------------------------------------------------------------
__global__ __launch_bounds__(96) void k2_qkv(
    const float* __restrict__ wq,  const float* __restrict__ bq,
    const float* __restrict__ wk,  const float* __restrict__ bk,
    const float* __restrict__ wv,  const float* __restrict__ bv,
    const float* __restrict__ wqs, const float* __restrict__ bqs,
    const float* __restrict__ wks, const float* __restrict__ bks,
    const float* __restrict__ wvs, const float* __restrict__ bvs,
    const float* __restrict__ off, const float* __restrict__ offc)
{
    const int n = blockIdx.x, b = blockIdx.y;
    const int t = n / (tH * tW);
    __shared__ float xs[CD], xcs[CD];
    const int tid = threadIdx.x;
    if (tid < 32)        xs[tid]       = g_xd[0][b][n][tid];
    else if (tid < 64)   xcs[tid - 32] = g_xd[1][b][n][tid - 32];
    __syncthreads();

    if (tid < 32) {
        int role = tid >> 3, j = tid & 7;
        const float* src = (role == 0) ? xs : xcs;
        const float *Wm, *Bm, *op;
        if      (role == 0) { Wm = wq;  Bm = bq;  op = off;  }
        else if (role == 1) { Wm = wk;  Bm = bk;  op = offc; }
        else if (role == 2) { Wm = wqs; Bm = bqs; op = off;  }
        else                { Wm = wks; Bm = bks; op = off;  }
        float x1 = Bm[j], x2 = Bm[j + 8];
        #pragma unroll 8
        for (int c = 0; c < 32; ++c) {
            float xv = src[c];
            x1 += Wm[j * 32 + c] * xv;
            x2 += Wm[(j + 8) * 32 + c] * xv;
        }
        float invf = __powf(10000.0f, -((float)(2 * j)) / 16.0f);
        float arg  = (float)t * invf;
        float o    = op[j * 500 + t];
        float sv = sinf(arg) + o;
        float cv = cosf(arg) + o;
        float o1 = x1 * cv - x2 * sv;
        float o2 = x2 * cv + x1 * sv;
        if (role == 0)      { g_q[0][b][n][j] = o1 * 0.5f; g_q[0][b][n][j+8] = o2 * 0.5f; }
        else if (role == 1) { g_k[0][b][n][j] = o1;        g_k[0][b][n][j+8] = o2; }
        else if (role == 2) { g_q[1][b][n][j] = o1 * 0.5f; g_q[1][b][n][j+8] = o2 * 0.5f; }
        else                { g_k[1][b][n][j] = o1;        g_k[1][b][n][j+8] = o2; }
    } else {
        int av = (tid >= 64) ? 1 : 0;
        int c  = tid - 32 - av * 32;
        const float* Wm = av ? wvs : wv;
        const float* Bm = av ? bvs : bv;
        float acc = Bm[c];
        #pragma unroll 8
        for (int ci = 0; ci < 32; ++ci) acc += Wm[c * 32 + ci] * xcs[ci];
        g_v[av][b][n][c] = acc;
    }
}

// ---------------------------------------------------------------------------
// Kernel 3: attention. One block = 64 query rows, loops 72 tiles of 64 keys.
// Softmax without max-subtraction (scores bounded, |s| < ~3).
// grid (72, 4), block 128.
// ---------------------------------------------------------------------------
__global__ __launch_bounds__(128) void k3_attn()
{
    const int a = blockIdx.y >> 1, b = blockIdx.y & 1;
    const int row0 = blockIdx.x * 64;
    const float* Q = &g_q[a][b][0][0];
    const float* K = &g_k[a][b][0][0];
    const float* V = &g_v[a][b][0][0];

    __shared__ float Qs[CQ][64];
    __shared__ float Ks[CQ][64];
    __shared__ float Vs[64][CV];
    __shared__ float Ss[64][65];      // scores -> probabilities in place
    __shared__ float Lrow[64];

    const int tid = threadIdx.x;
    const int rg = tid >> 3;          // 0..15 : 4 rows each
    const int mg = tid & 7;           // 0..7  : 8 score cols / 4 PV cols

    // Q tile transposed into smem
    for (int e = tid; e < 256; e += 128) {
        int m = e >> 2, c4 = (e & 3) << 2;
        float4 qv = *(const float4*)(Q + (size_t)(row0 + m) * CQ + c4);
        Qs[c4][m] = qv.x; Qs[c4+1][m] = qv.y; Qs[c4+2][m] = qv.z; Qs[c4+3][m] = qv.w;
    }

    float acc[4][4];
    #pragma unroll
    for (int i = 0; i < 4; ++i)
        #pragma unroll
        for (int j = 0; j < 4; ++j) acc[i][j] = 0.f;
    float lsum = 0.f;

    __syncthreads();

    for (int mt = 0; mt < NTOK / 64; ++mt) {
        const int m0 = mt * 64;
        for (int e = tid; e < 256; e += 128) {
            int m = e >> 2, c4 = (e & 3) << 2;
            float4 kv = *(const float4*)(K + (size_t)(m0 + m) * CQ + c4);
            Ks[c4][m] = kv.x; Ks[c4+1][m] = kv.y; Ks[c4+2][m] = kv.z; Ks[c4+3][m] = kv.w;
        }
        for (int e = tid; e < 512; e += 128) {
            int m = e >> 3, c4 = (e & 7) << 2;
            *(float4*)&Vs[m][c4] = *(const float4*)(V + (size_t)(m0 + m) * CV + c4);
        }
        __syncthreads();

        // ---- scores: S[rg*4+i][mg*8+j] = q . k (q pre-scaled by 1/2) ----
        float s[4][8];
        #pragma unroll
        for (int i = 0; i < 4; ++i)
            #pragma unroll
            for (int j = 0; j < 8; ++j) s[i][j] = 0.f;
        #pragma unroll 4
        for (int c = 0; c < CQ; ++c) {
            float4 qv = *(const float4*)&Qs[c][rg << 2];
            float4 k0 = *(const float4*)&Ks[c][mg << 3];
            float4 k1 = *(const float4*)&Ks[c][(mg << 3) + 4];
            float qa[4] = {qv.x, qv.y, qv.z, qv.w};
            float kb[8] = {k0.x, k0.y, k0.z, k0.w, k1.x, k1.y, k1.z, k1.w};
            #pragma unroll
            for (int i = 0; i < 4; ++i)
                #pragma unroll
                for (int j = 0; j < 8; ++j)
                    s[i][j] += qa[i] * kb[j];
        }
        #pragma unroll
        for (int i = 0; i < 4; ++i)
            #pragma unroll
            for (int j = 0; j < 8; ++j)
                Ss[(rg << 2) + i][(mg << 3) + j] = s[i][j];
        __syncthreads();

        // ---- exp in place + row partial sums (threads 0..63, one row each) ----
        if (tid < 64) {
            float rsum = 0.f;
            #pragma unroll 8
            for (int m = 0; m < 64; ++m) {
                float p = __expf(Ss[tid][m]);
                Ss[tid][m] = p;
                rsum += p;
            }
            lsum += rsum;
        }
        __syncthreads();

        // ---- PV: acc[rg*4+i][mg*4+j] += P[r][m] * V[m][c] ----
        const int rg4 = rg << 2;
        #pragma unroll 8
        for (int m = 0; m < 64; ++m) {
            float4 vv = *(const float4*)&Vs[m][mg << 2];
            float p0 = Ss[rg4 + 0][m];
            float p1 = Ss[rg4 + 1][m];
            float p2 = Ss[rg4 + 2][m];
            float p3 = Ss[rg4 + 3][m];
            acc[0][0] += p0 * vv.x; acc[0][1] += p0 * vv.y; acc[0][2] += p0 * vv.z; acc[0][3] += p0 * vv.w;
            acc[1][0] += p1 * vv.x; acc[1][1] += p1 * vv.y; acc[1][2] += p1 * vv.z; acc[1][3] += p1 * vv.w;
            acc[2][0] += p2 * vv.x; acc[2][1] += p2 * vv.y; acc[2][2] += p2 * vv.z; acc[2][3] += p2 * vv.w;
            acc[3][0] += p3 * vv.x; acc[3][1] += p3 * vv.y; acc[3][2] += p3 * vv.z; acc[3][3] += p3 * vv.w;
        }
        __syncthreads();
    }

    if (tid < 64) Lrow[tid] = lsum;
    __syncthreads();
    #pragma unroll
    for (int i = 0; i < 4; ++i) {
        int r = (rg << 2) + i;
        float inv = 1.f / Lrow[r];
        float4 o = make_float4(acc[i][0]*inv, acc[i][1]*inv, acc[i][2]*inv, acc[i][3]*inv);
        *(float4*)&g_o[a][b][row0 + r][mg << 2] = o;
    }
}

// ---------------------------------------------------------------------------
// Kernel 4: groupnorm stats (mean/var over all C,T,H,W per batch). grid 4.
// ---------------------------------------------------------------------------
__global__ __launch_bounds__(512) void k4_stats()
{
    const int a = blockIdx.x >> 1, b = blockIdx.x & 1;
    const float* p = &g_o[a][b][0][0];
    const int tot = NTOK * CV;
    float s = 0.f, ss = 0.f;
    for (int i = threadIdx.x; i < tot; i += 512) {
        float v = p[i]; s += v; ss += v * v;
    }
    __shared__ float rs[512], rss[512];
    rs[threadIdx.x] = s; rss[threadIdx.x] = ss;
    __syncthreads();
    for (int st = 256; st > 0; st >>= 1) {
        if (threadIdx.x < st) {
            rs[threadIdx.x]  += rs[threadIdx.x + st];
            rss[threadIdx.x] += rss[threadIdx.x + st];
        }
        __syncthreads();
    }
    if (threadIdx.x == 0) {
        float inv = 1.f / (float)tot;
        float mu  = rs[0] * inv;
        float var = rss[0] * inv - mu * mu;
        g_mu[a][b] = mu;
        g_rs[a][b] = rsqrtf(var + 1e-5f);
    }
}

// ---------------------------------------------------------------------------
// Kernel 5: groupnorm apply + 1x1 up-conv 32->64. grid (NTOK, B_), block 128.
// ---------------------------------------------------------------------------
__global__ __launch_bounds__(128) void k5_gnup(
    const float* __restrict__ gw,  const float* __restrict__ gb,
    const float* __restrict__ gws, const float* __restrict__ gbs,
    const float* __restrict__ wu,  const float* __restrict__ bu,
    const float* __restrict__ wus, const float* __restrict__ bus)
{
    const int n = blockIdx.x, b = blockIdx.y;
    __shared__ float h0[CV], h1[CV];
    const int tid = threadIdx.x;
    if (tid < 32) {
        h0[tid] = (g_o[0][b][n][tid] - g_mu[0][b]) * g_rs[0][b] * gw[tid] + gb[tid];
    } else if (tid < 64) {
        int c = tid - 32;
        h1[c] = (g_o[1][b][n][c] - g_mu[1][b]) * g_rs[1][b] * gws[c] + gbs[c];
    }
    __syncthreads();
    if (tid < 64) {
        float acc = bu[tid];
        #pragma unroll 8
        for (int c = 0; c < 32; ++c) acc += wu[tid * 32 + c] * h0[c];
        g_u[0][b][tid][n] = acc;
    } else {
        int co = tid - 64;
        float acc = bus[co];
        #pragma unroll 8
        for (int c = 0; c < 32; ++c) acc += wus[co * 32 + c] * h1[c];
        g_u[1][b][co][n] = acc;
    }
}

// ---------------------------------------------------------------------------
// Kernel 6: trilinear upsample (8,24,24)->(16,48,48) of both branches + combine
// ---------------------------------------------------------------------------
__global__ __launch_bounds__(256) void k6_final(
    const float* __restrict__ xc, float* __restrict__ out)
{
    int idx = blockIdx.x * blockDim.x + threadIdx.x;
    if (idx >= NOUT) return;
    int w = idx % W_IN;
    int h = (idx / W_IN) % H_IN;
    int t = (idx / (W_IN * H_IN)) % T_IN;
    int c = (idx / (W_IN * H_IN * T_IN)) % C_IN;
    int b = idx / (W_IN * H_IN * T_IN * C_IN);

    const float st = (float)(7.0 / 15.0);
    const float sw = (float)(23.0 / 47.0);

    float pt = (float)t * st;
    int t0 = (int)floorf(pt); t0 = t0 < 0 ? 0 : (t0 > tT-1 ? tT-1 : t0);
    int t1 = t0 + 1 > tT-1 ? tT-1 : t0 + 1;
    float ft = pt - (float)t0;

    float ph = (float)h * sw;
    int h0 = (int)floorf(ph); h0 = h0 < 0 ? 0 : (h0 > tH-1 ? tH-1 : h0);
    int h1 = h0 + 1 > tH-1 ? tH-1 : h0 + 1;
    float fh = ph - (float)h0;

    float pw = (float)w * sw;
    int w0 = (int)floorf(pw); w0 = w0 < 0 ? 0 : (w0 > tW-1 ? tW-1 : w0);
    int w1 = w0 + 1 > tW-1 ? tW-1 : w0 + 1;
    float fw = pw - (float)w0;

    int i00 = (t0 * tH + h0) * tW;
    int i01 = (t0 * tH + h1) * tW;
    int i10 = (t1 * tH + h0) * tW;
    int i11 = (t1 * tH + h1) * tW;

    float r[2];
    #pragma unroll
    for (int a = 0; a < 2; ++a) {
        const float* U = &g_u[a][b][c][0];
        float v00 = U[i00 + w0] + (U[i00 + w1] - U[i00 + w0]) * fw;
        float v01 = U[i01 + w0] + (U[i01 + w1] - U[i01 + w0]) * fw;
        float v10 = U[i10 + w0] + (U[i10 + w1] - U[i10 + w0]) * fw;
        float v11 = U[i11 + w0] + (U[i11 + w1] - U[i11 + w0]) * fw;
        float v0 = v00 + (v01 - v00) * fh;
        float v1 = v10 + (v11 - v10) * fh;
        r[a] = v0 + (v1 - v0) * ft;
    }
    out[idx] = xc[idx] + r[1] - 0.5f * r[0];
}

// ---------------------------------------------------------------------------
extern "C" void kernel_launch(void* const* d_in, const int* in_sizes, int n_in,
                              void* d_out, int out_size)
{
    const float* x        = (const float*)d_in[0];
    const float* x_c      = (const float*)d_in[1];
    const float* w_down   = (const float*)d_in[2];
    const float* b_down   = (const float*)d_in[3];
    const float* w_down_c = (const float*)d_in[4];
    const float* b_down_c = (const float*)d_in[5];
    const float* w_q      = (const float*)d_in[6];
    const float* b_q      = (const float*)d_in[7];
    const float* w_k      = (const float*)d_in[8];
    const float* b_k      = (const float*)d_in[9];
    const float* w_v      = (const float*)d_in[10];
    const float* b_v      = (const float*)d_in[11];
    const float* w_q_sa   = (const float*)d_in[12];
    const float* b_q_sa   = (const float*)d_in[13];
    const float* w_k_sa   = (const float*)d_in[14];
    const float* b_k_sa   = (const float*)d_in[15];
    const float* w_v_sa   = (const float*)d_in[16];
    const float* b_v_sa   = (const float*)d_in[17];
    const float* gn_w     = (const float*)d_in[18];
    const float* gn_b     = (const float*)d_in[19];
    const float* gn_w_sa  = (const float*)d_in[20];
    const float* gn_b_sa  = (const float*)d_in[21];
    const float* w_up     = (const float*)d_in[22];
    const float* b_up     = (const float*)d_in[23];
    const float* w_up_sa  = (const float*)d_in[24];
    const float* b_up_sa  = (const float*)d_in[25];
    const float* offset   = (const float*)d_in[26];
    const float* offset_c = (const float*)d_in[27];

    dim3 g1(tT * tH, B_, 2);
    k1_down<<<g1, 128>>>(x, x_c, w_down, b_down, w_down_c, b_down_c);

    dim3 g2(NTOK, B_);
    k2_qkv<<<g2, 96>>>(w_q, b_q, w_k, b_k, w_v, b_v,
                       w_q_sa, b_q_sa, w_k_sa, b_k_sa, w_v_sa, b_v_sa,
                       offset, offset_c);

    dim3 g3(NTOK / 64, 4);
    k3_attn<<<g3, 128>>>();

    k4_stats<<<4, 512>>>();

    dim3 g5(NTOK, B_);
    k5_gnup<<<g5, 128>>>(gn_w, gn_b, gn_w_sa, gn_b_sa,
                         w_up, b_up, w_up_sa, b_up_sa);

    k6_final<<<(NOUT + 255) / 256, 256>>>(x_c, (float*)d_out);
}